// round 5
// baseline (speedup 1.0000x reference)
#include <cuda_runtime.h>
#include <cuda_bf16.h>
#include <cstdint>

// Problem constants
#define EMB   1024
#define NH    16
#define HD    64
#define BATCH 4
#define SEQ   1024
#define MTOT  (BATCH*SEQ)
#define SCALING 0.3952847075210474f   // (64*0.1)^-0.5
#define NEG   (-1e30f)

// Scratch (device globals)
__device__ float g_qkv[MTOT * 3 * EMB];
__device__ __nv_bfloat16 g_A_hi[MTOT * EMB];
__device__ __nv_bfloat16 g_A_lo[MTOT * EMB];
__device__ __nv_bfloat16 g_W1_hi[3 * EMB * EMB];
__device__ __nv_bfloat16 g_W1_lo[3 * EMB * EMB];
__device__ __nv_bfloat16 g_W2_hi[EMB * EMB];
__device__ __nv_bfloat16 g_W2_lo[EMB * EMB];
__device__ __nv_bfloat16 g_att_hi[MTOT * EMB];
__device__ __nv_bfloat16 g_att_lo[MTOT * EMB];
__device__ __nv_bfloat16 g_Qh[MTOT * EMB];
__device__ __nv_bfloat16 g_Ql[MTOT * EMB];
__device__ __nv_bfloat16 g_Kh[MTOT * EMB];
__device__ __nv_bfloat16 g_Kl[MTOT * EMB];
__device__ __nv_bfloat16 g_Vh[MTOT * EMB];
__device__ __nv_bfloat16 g_Vl[MTOT * EMB];

// ---------------------------------------------------------------------------
// PTX helpers
// ---------------------------------------------------------------------------
#define LDSM4(r, addr) \
    asm volatile("ldmatrix.sync.aligned.m8n8.x4.shared.b16 {%0,%1,%2,%3}, [%4];" \
                 : "=r"((r)[0]), "=r"((r)[1]), "=r"((r)[2]), "=r"((r)[3]) : "r"(addr))

#define LDSM4T(r, addr) \
    asm volatile("ldmatrix.sync.aligned.m8n8.x4.trans.shared.b16 {%0,%1,%2,%3}, [%4];" \
                 : "=r"((r)[0]), "=r"((r)[1]), "=r"((r)[2]), "=r"((r)[3]) : "r"(addr))

#define MMA_BF16(d, a, b) \
    asm volatile("mma.sync.aligned.m16n8k16.row.col.f32.bf16.bf16.f32 " \
                 "{%0,%1,%2,%3},{%4,%5,%6,%7},{%8,%9},{%0,%1,%2,%3};" \
                 : "+f"((d)[0]), "+f"((d)[1]), "+f"((d)[2]), "+f"((d)[3]) \
                 : "r"((a)[0]), "r"((a)[1]), "r"((a)[2]), "r"((a)[3]), \
                   "r"((b)[0]), "r"((b)[1]))

__device__ __forceinline__ void cp16(uint32_t s, const void* g) {
    asm volatile("cp.async.cg.shared.global [%0], [%1], 16;" :: "r"(s), "l"(g));
}

__device__ __forceinline__ uint32_t packbf(float lo, float hi) {
    uint32_t r;
    asm("cvt.rn.bf16x2.f32 %0, %1, %2;" : "=r"(r) : "f"(hi), "f"(lo));
    return r;
}
__device__ __forceinline__ uint32_t residpack(uint32_t ph, float lo, float hi) {
    float h_lo = __uint_as_float(ph << 16);
    float h_hi = __uint_as_float(ph & 0xffff0000u);
    return packbf(lo - h_lo, hi - h_hi);
}

// ---------------------------------------------------------------------------
// f32 -> bf16 (hi, lo) split
// ---------------------------------------------------------------------------
__global__ __launch_bounds__(256)
void split_kernel(const float* __restrict__ in,
                  __nv_bfloat16* __restrict__ hi,
                  __nv_bfloat16* __restrict__ lo, int n)
{
    int i = (blockIdx.x * blockDim.x + threadIdx.x) * 4;
    if (i >= n) return;
    float4 v = *(const float4*)(in + i);
    float f[4] = {v.x, v.y, v.z, v.w};
    __nv_bfloat16 h[4], l[4];
#pragma unroll
    for (int j = 0; j < 4; j++) {
        h[j] = __float2bfloat16(f[j]);
        l[j] = __float2bfloat16(f[j] - __bfloat162float(h[j]));
    }
    *(uint2*)(hi + i) = *(const uint2*)h;
    *(uint2*)(lo + i) = *(const uint2*)l;
}

// ---------------------------------------------------------------------------
// qkv f32 -> head-major bf16 hi/lo [b,h,s,64]; Q pre-scaled
// ---------------------------------------------------------------------------
__global__ __launch_bounds__(256)
void qkv_split(const float* __restrict__ qkv,
               __nv_bfloat16* __restrict__ Qh, __nv_bfloat16* __restrict__ Ql,
               __nv_bfloat16* __restrict__ Kh, __nv_bfloat16* __restrict__ Kl,
               __nv_bfloat16* __restrict__ Vh, __nv_bfloat16* __restrict__ Vl)
{
    int m = blockIdx.y;
    int i = (blockIdx.x * 256 + threadIdx.x) * 4;
    int row = i >> 10, col = i & 1023;
    float4 v = *(const float4*)(qkv + (size_t)row * 3072 + m * 1024 + col);
    if (m == 0) { v.x *= SCALING; v.y *= SCALING; v.z *= SCALING; v.w *= SCALING; }
    int bb = row >> 10, s = row & 1023, hh = col >> 6, d = col & 63;
    size_t o = (((size_t)(bb * NH + hh)) * SEQ + s) * HD + d;
    __nv_bfloat16* hi = (m == 0) ? Qh : (m == 1) ? Kh : Vh;
    __nv_bfloat16* lo = (m == 0) ? Ql : (m == 1) ? Kl : Vl;
    float f[4] = {v.x, v.y, v.z, v.w};
    __nv_bfloat16 hb4[4], lb4[4];
#pragma unroll
    for (int j = 0; j < 4; j++) {
        hb4[j] = __float2bfloat16(f[j]);
        lb4[j] = __float2bfloat16(f[j] - __bfloat162float(hb4[j]));
    }
    *(uint2*)(hi + o) = *(const uint2*)hb4;
    *(uint2*)(lo + o) = *(const uint2*)lb4;
}

// ---------------------------------------------------------------------------
// Tensor-core GEMM: C[M,N] = A[M,K]*B[N,K]^T + bias[N], 3-term bf16 split.
// 128x128 tile, BK=32, 256 threads (8 warps: 4m x 2n), warp tile 32m x 64n.
// MMA issue is term-outer: 16 independent accumulators between dependent reuses.
// ---------------------------------------------------------------------------
#define AST   40
#define STG_H (128 * AST)

__global__ __launch_bounds__(256)
void gemm_mma(const __nv_bfloat16* __restrict__ Ah,
              const __nv_bfloat16* __restrict__ Al,
              const __nv_bfloat16* __restrict__ Bh,
              const __nv_bfloat16* __restrict__ Bl,
              const float* __restrict__ bias,
              float* __restrict__ C, int M, int N, int K)
{
    extern __shared__ __align__(16) __nv_bfloat16 smem_b[];
    const uint32_t sm_base = (uint32_t)__cvta_generic_to_shared(smem_b);

    const int t    = threadIdx.x;
    const int lane = t & 31;
    const int w    = t >> 5;
    const int wm   = w & 3;
    const int wn   = w >> 2;
    const int bm   = blockIdx.y * 128;
    const int bn   = blockIdx.x * 128;
    const int nk   = K >> 5;

    float acc[2][8][4];
#pragma unroll
    for (int mi = 0; mi < 2; mi++)
#pragma unroll
        for (int ni = 0; ni < 8; ni++)
#pragma unroll
            for (int q = 0; q < 4; q++) acc[mi][ni][q] = 0.f;

    const int c0row = (t + 0)   >> 2, c0k = ((t + 0)   & 3) * 8;
    const int c1row = (t + 256) >> 2, c1k = ((t + 256) & 3) * 8;

    const __nv_bfloat16* gp[4] = {Ah, Al, Bh, Bl};

    auto issue = [&](int stage, int k0) {
#pragma unroll
        for (int m = 0; m < 4; m++) {
            int base = (m < 2) ? bm : bn;
            const __nv_bfloat16* g = gp[m];
            uint32_t so = sm_base + (uint32_t)(stage * 4 + m) * STG_H * 2;
            cp16(so + (uint32_t)(c0row * AST + c0k) * 2,
                 g + (size_t)(base + c0row) * K + k0 + c0k);
            cp16(so + (uint32_t)(c1row * AST + c1k) * 2,
                 g + (size_t)(base + c1row) * K + k0 + c1k);
        }
        asm volatile("cp.async.commit_group;");
    };

    issue(0, 0);

    for (int kt = 0; kt < nk; kt++) {
        if (kt + 1 < nk) {
            issue((kt + 1) & 1, (kt + 1) << 5);
            asm volatile("cp.async.wait_group 1;");
        } else {
            asm volatile("cp.async.wait_group 0;");
        }
        __syncthreads();

        const int stage = kt & 1;
        const uint32_t bAh = sm_base + (uint32_t)(stage * 4 + 0) * STG_H * 2;
        const uint32_t bAl = sm_base + (uint32_t)(stage * 4 + 1) * STG_H * 2;
        const uint32_t bBh = sm_base + (uint32_t)(stage * 4 + 2) * STG_H * 2;
        const uint32_t bBl = sm_base + (uint32_t)(stage * 4 + 3) * STG_H * 2;

#pragma unroll
        for (int ks = 0; ks < 2; ks++) {
            uint32_t ah[2][4], al[2][4], bh[8][2], bl[8][2];

            const int arow = wm * 32 + (lane & 15);
            const int acol = ks * 16 + (lane >> 4) * 8;
#pragma unroll
            for (int mi = 0; mi < 2; mi++) {
                uint32_t off = (uint32_t)((arow + mi * 16) * AST + acol) * 2;
                LDSM4(ah[mi], bAh + off);
                LDSM4(al[mi], bAl + off);
            }

            const int brow = wn * 64 + (lane >> 4) * 8 + (lane & 7);
            const int bcol = ks * 16 + ((lane >> 3) & 1) * 8;
#pragma unroll
            for (int ni2 = 0; ni2 < 4; ni2++) {
                uint32_t off = (uint32_t)((brow + ni2 * 16) * AST + bcol) * 2;
                uint32_t r[4];
                LDSM4(r, bBh + off);
                bh[ni2 * 2][0] = r[0]; bh[ni2 * 2][1] = r[1];
                bh[ni2 * 2 + 1][0] = r[2]; bh[ni2 * 2 + 1][1] = r[3];
                LDSM4(r, bBl + off);
                bl[ni2 * 2][0] = r[0]; bl[ni2 * 2][1] = r[1];
                bl[ni2 * 2 + 1][0] = r[2]; bl[ni2 * 2 + 1][1] = r[3];
            }

            // term-outer issue: 16 independent accs between dependent reuses
#pragma unroll
            for (int mi = 0; mi < 2; mi++)
#pragma unroll
                for (int ni = 0; ni < 8; ni++)
                    MMA_BF16(acc[mi][ni], ah[mi], bh[ni]);   // hi*hi
#pragma unroll
            for (int mi = 0; mi < 2; mi++)
#pragma unroll
                for (int ni = 0; ni < 8; ni++)
                    MMA_BF16(acc[mi][ni], al[mi], bh[ni]);   // lo*hi
#pragma unroll
            for (int mi = 0; mi < 2; mi++)
#pragma unroll
                for (int ni = 0; ni < 8; ni++)
                    MMA_BF16(acc[mi][ni], ah[mi], bl[ni]);   // hi*lo
        }
        __syncthreads();
    }

#pragma unroll
    for (int mi = 0; mi < 2; mi++) {
        const int r0 = bm + wm * 32 + mi * 16 + (lane >> 2);
#pragma unroll
        for (int ni = 0; ni < 8; ni++) {
            const int col = bn + wn * 64 + ni * 8 + (lane & 3) * 2;
            float bx = bias[col], by = bias[col + 1];
            float2 v0 = make_float2(acc[mi][ni][0] + bx, acc[mi][ni][1] + by);
            float2 v1 = make_float2(acc[mi][ni][2] + bx, acc[mi][ni][3] + by);
            *(float2*)&C[(size_t)r0 * N + col] = v0;
            *(float2*)&C[(size_t)(r0 + 8) * N + col] = v1;
        }
    }
}

// ---------------------------------------------------------------------------
// Tensor-core flash attention; term-outer MMA issue; bf16 hi/lo epilogue.
// ---------------------------------------------------------------------------
#define AT_ST 72
#define Q_HI_B 0
#define Q_LO_B 18432
#define TILE_B 36864
#define MAT_B  9216
#define BUF_B  36864
#define ATT_SMEM 110592

__global__ __launch_bounds__(256)
void attn_mma(const float* __restrict__ bias, const unsigned char* __restrict__ mask,
              __nv_bfloat16* __restrict__ outh, __nv_bfloat16* __restrict__ outl,
              const __nv_bfloat16* __restrict__ Qh, const __nv_bfloat16* __restrict__ Ql,
              const __nv_bfloat16* __restrict__ Kh, const __nv_bfloat16* __restrict__ Kl,
              const __nv_bfloat16* __restrict__ Vh, const __nv_bfloat16* __restrict__ Vl)
{
    extern __shared__ __align__(16) __nv_bfloat16 smA[];
    const uint32_t s_base = (uint32_t)__cvta_generic_to_shared(smA);

    const int t = threadIdx.x, lane = t & 31, wid = t >> 5;
    const int qt = blockIdx.x, h = blockIdx.y, b = blockIdx.z;
    const int qbase = qt * 128;
    const size_t hb = (size_t)(b * NH + h) * SEQ * HD;

    const int lr7 = lane & 7, l8 = (lane >> 3) & 1, l16 = lane >> 4;

    const __nv_bfloat16* qsrc[2] = {Qh, Ql};
    const __nv_bfloat16* ksrc[4] = {Kh, Kl, Vh, Vl};

#pragma unroll
    for (int it = 0; it < 8; it++) {
        int c = t + it * 256;
        int mat = c >> 10, r = (c >> 3) & 127, ck = c & 7;
        cp16(s_base + mat * Q_LO_B + (uint32_t)(r * AT_ST + ck * 8) * 2,
             qsrc[mat] + hb + (size_t)(qbase + r) * HD + ck * 8);
    }
#pragma unroll
    for (int it = 0; it < 8; it++) {
        int c = t + it * 256;
        int mat = c >> 9, r = (c >> 3) & 63, ck = c & 7;
        cp16(s_base + TILE_B + mat * MAT_B + (uint32_t)(r * AT_ST + ck * 8) * 2,
             ksrc[mat] + hb + (size_t)r * HD + ck * 8);
    }
    asm volatile("cp.async.commit_group;");
#pragma unroll
    for (int it = 0; it < 8; it++) {
        int c = t + it * 256;
        int mat = c >> 9, r = (c >> 3) & 63, ck = c & 7;
        cp16(s_base + TILE_B + BUF_B + mat * MAT_B + (uint32_t)(r * AT_ST + ck * 8) * 2,
             ksrc[mat] + hb + (size_t)(64 + r) * HD + ck * 8);
    }
    asm volatile("cp.async.commit_group;");
    asm volatile("cp.async.wait_group 1;");
    __syncthreads();

    uint32_t aqh[4][4], aql[4][4];
    {
        const int arow = wid * 16 + (lane & 15);
        const int acol = 8 * l16;
#pragma unroll
        for (int ks = 0; ks < 4; ks++) {
            uint32_t off = (uint32_t)(arow * AT_ST + ks * 16 + acol) * 2;
            LDSM4(aqh[ks], s_base + Q_HI_B + off);
            LDSM4(aql[ks], s_base + Q_LO_B + off);
        }
    }

    float O[8][4];
#pragma unroll
    for (int nf = 0; nf < 8; nf++)
#pragma unroll
        for (int q = 0; q < 4; q++) O[nf][q] = 0.f;
    float m0 = NEG, m1 = NEG, l0 = 0.f, l1 = 0.f;

    const float* bp = bias + (size_t)(b * NH + h) * SEQ * SEQ;
    const unsigned char* mrow = mask + (size_t)b * SEQ;
    const int qr = qbase + wid * 16 + (lane >> 2);
    const int colb = 2 * (lane & 3);

    const int krow = lr7 + 8 * l16;
    const int kcol = 8 * l8;
    const int vrow = lr7 + 8 * l8;
    const int vcol = 8 * l16;

    for (int kt = 0; kt < 16; kt++) {
        const uint32_t tb = s_base + TILE_B + (uint32_t)(kt & 1) * BUF_B;

        float2 bv0[8], bv1[8];
        uchar2 mk[8];
#pragma unroll
        for (int nf = 0; nf < 8; nf++) {
            int col = kt * 64 + nf * 8 + colb;
            bv0[nf] = *(const float2*)&bp[(size_t)qr * SEQ + col];
            bv1[nf] = *(const float2*)&bp[(size_t)(qr + 8) * SEQ + col];
            mk[nf]  = *(const uchar2*)&mrow[col];
        }

        float s[8][4];
#pragma unroll
        for (int nf = 0; nf < 8; nf++)
#pragma unroll
            for (int q = 0; q < 4; q++) s[nf][q] = 0.f;

#pragma unroll
        for (int ks = 0; ks < 4; ks++) {
            uint32_t bh[8][2], bl[8][2];
#pragma unroll
            for (int nf2 = 0; nf2 < 4; nf2++) {
                uint32_t off = (uint32_t)((nf2 * 16 + krow) * AT_ST + ks * 16 + kcol) * 2;
                uint32_t r4[4];
                LDSM4(r4, tb + 0 * MAT_B + off);
                bh[2*nf2][0] = r4[0]; bh[2*nf2][1] = r4[1];
                bh[2*nf2+1][0] = r4[2]; bh[2*nf2+1][1] = r4[3];
                LDSM4(r4, tb + 1 * MAT_B + off);
                bl[2*nf2][0] = r4[0]; bl[2*nf2][1] = r4[1];
                bl[2*nf2+1][0] = r4[2]; bl[2*nf2+1][1] = r4[3];
            }
            // term-outer: 8 independent s accs between dependent reuses
#pragma unroll
            for (int nf = 0; nf < 8; nf++)
                MMA_BF16(s[nf], aqh[ks], bh[nf]);
#pragma unroll
            for (int nf = 0; nf < 8; nf++)
                MMA_BF16(s[nf], aql[ks], bh[nf]);
#pragma unroll
            for (int nf = 0; nf < 8; nf++)
                MMA_BF16(s[nf], aqh[ks], bl[nf]);
        }

#pragma unroll
        for (int nf = 0; nf < 8; nf++) {
            s[nf][0] = mk[nf].x ? NEG : s[nf][0] + bv0[nf].x;
            s[nf][1] = mk[nf].y ? NEG : s[nf][1] + bv0[nf].y;
            s[nf][2] = mk[nf].x ? NEG : s[nf][2] + bv1[nf].x;
            s[nf][3] = mk[nf].y ? NEG : s[nf][3] + bv1[nf].y;
        }

        float mx0 = NEG, mx1 = NEG;
#pragma unroll
        for (int nf = 0; nf < 8; nf++) {
            mx0 = fmaxf(mx0, fmaxf(s[nf][0], s[nf][1]));
            mx1 = fmaxf(mx1, fmaxf(s[nf][2], s[nf][3]));
        }
        mx0 = fmaxf(mx0, __shfl_xor_sync(0xffffffffu, mx0, 1));
        mx0 = fmaxf(mx0, __shfl_xor_sync(0xffffffffu, mx0, 2));
        mx1 = fmaxf(mx1, __shfl_xor_sync(0xffffffffu, mx1, 1));
        mx1 = fmaxf(mx1, __shfl_xor_sync(0xffffffffu, mx1, 2));
        float mn0 = fmaxf(m0, mx0), mn1 = fmaxf(m1, mx1);
        float sc0 = __expf(m0 - mn0), sc1 = __expf(m1 - mn1);
        m0 = mn0; m1 = mn1;
        float su0 = 0.f, su1 = 0.f;
#pragma unroll
        for (int nf = 0; nf < 8; nf++) {
            s[nf][0] = __expf(s[nf][0] - mn0);
            s[nf][1] = __expf(s[nf][1] - mn0);
            s[nf][2] = __expf(s[nf][2] - mn1);
            s[nf][3] = __expf(s[nf][3] - mn1);
            su0 += s[nf][0] + s[nf][1];
            su1 += s[nf][2] + s[nf][3];
        }
        su0 += __shfl_xor_sync(0xffffffffu, su0, 1);
        su0 += __shfl_xor_sync(0xffffffffu, su0, 2);
        su1 += __shfl_xor_sync(0xffffffffu, su1, 1);
        su1 += __shfl_xor_sync(0xffffffffu, su1, 2);
        l0 = l0 * sc0 + su0;
        l1 = l1 * sc1 + su1;
#pragma unroll
        for (int nf = 0; nf < 8; nf++) {
            O[nf][0] *= sc0; O[nf][1] *= sc0;
            O[nf][2] *= sc1; O[nf][3] *= sc1;
        }

        // P fragments for all 4 ks chunks first, then term-outer MMA issue
        uint32_t aph[4][4], apl[4][4];
#pragma unroll
        for (int ks = 0; ks < 4; ks++) {
            const float* p0 = s[2 * ks];
            const float* p1 = s[2 * ks + 1];
            aph[ks][0] = packbf(p0[0], p0[1]);
            aph[ks][1] = packbf(p0[2], p0[3]);
            aph[ks][2] = packbf(p1[0], p1[1]);
            aph[ks][3] = packbf(p1[2], p1[3]);
            apl[ks][0] = residpack(aph[ks][0], p0[0], p0[1]);
            apl[ks][1] = residpack(aph[ks][1], p0[2], p0[3]);
            apl[ks][2] = residpack(aph[ks][2], p1[0], p1[1]);
            apl[ks][3] = residpack(aph[ks][3], p1[2], p1[3]);
        }

#pragma unroll
        for (int ks = 0; ks < 4; ks++) {
            uint32_t vh[8][2], vl[8][2];
#pragma unroll
            for (int nf2 = 0; nf2 < 4; nf2++) {
                uint32_t off = (uint32_t)((ks * 16 + vrow) * AT_ST + nf2 * 16 + vcol) * 2;
                uint32_t r4[4];
                LDSM4T(r4, tb + 2 * MAT_B + off);
                vh[2*nf2][0] = r4[0]; vh[2*nf2][1] = r4[1];
                vh[2*nf2+1][0] = r4[2]; vh[2*nf2+1][1] = r4[3];
                LDSM4T(r4, tb + 3 * MAT_B + off);
                vl[2*nf2][0] = r4[0]; vl[2*nf2][1] = r4[1];
                vl[2*nf2+1][0] = r4[2]; vl[2*nf2+1][1] = r4[3];
            }
            // term-outer: 8 independent O accs between dependent reuses
#pragma unroll
            for (int nf = 0; nf < 8; nf++)
                MMA_BF16(O[nf], aph[ks], vh[nf]);
#pragma unroll
            for (int nf = 0; nf < 8; nf++)
                MMA_BF16(O[nf], apl[ks], vh[nf]);
#pragma unroll
            for (int nf = 0; nf < 8; nf++)
                MMA_BF16(O[nf], aph[ks], vl[nf]);
        }

        __syncthreads();
        if (kt + 2 < 16) {
#pragma unroll
            for (int it = 0; it < 8; it++) {
                int c = t + it * 256;
                int mat = c >> 9, r = (c >> 3) & 63, ck = c & 7;
                cp16(s_base + TILE_B + (uint32_t)(kt & 1) * BUF_B + mat * MAT_B +
                         (uint32_t)(r * AT_ST + ck * 8) * 2,
                     ksrc[mat] + hb + (size_t)((kt + 2) * 64 + r) * HD + ck * 8);
            }
            asm volatile("cp.async.commit_group;");
        }
        if (kt + 1 < 16) {
            if (kt + 2 < 16) asm volatile("cp.async.wait_group 1;");
            else             asm volatile("cp.async.wait_group 0;");
            __syncthreads();
        }
    }

    // epilogue: write bf16 hi/lo directly (feeds out-proj GEMM, no split pass)
    float i0 = 1.f / l0, i1 = 1.f / l1;
    int orow = b * SEQ + qbase + wid * 16 + (lane >> 2);
    uint32_t* oh = (uint32_t*)outh;
    uint32_t* ol = (uint32_t*)outl;
#pragma unroll
    for (int nf = 0; nf < 8; nf++) {
        int col = h * HD + nf * 8 + colb;
        float a0 = O[nf][0] * i0, a1 = O[nf][1] * i0;
        float b0 = O[nf][2] * i1, b1 = O[nf][3] * i1;
        uint32_t h0 = packbf(a0, a1);
        uint32_t l0r = residpack(h0, a0, a1);
        uint32_t h1 = packbf(b0, b1);
        uint32_t l1r = residpack(h1, b0, b1);
        size_t idx0 = ((size_t)orow * EMB + col) >> 1;
        size_t idx1 = ((size_t)(orow + 8) * EMB + col) >> 1;
        oh[idx0] = h0; ol[idx0] = l0r;
        oh[idx1] = h1; ol[idx1] = l1r;
    }
}

// ---------------------------------------------------------------------------
extern "C" void kernel_launch(void* const* d_in, const int* in_sizes, int n_in,
                              void* d_out, int out_size)
{
    const float* query         = (const float*)d_in[0];
    const unsigned char* maskp = (const unsigned char*)d_in[1];
    const float* attn_bias     = (const float*)d_in[2];
    const float* Wqkv          = (const float*)d_in[3];
    const float* bqkv          = (const float*)d_in[4];
    const float* Wo            = (const float*)d_in[5];
    const float* bo            = (const float*)d_in[6];
    float* out                 = (float*)d_out;

    float* qkv;
    __nv_bfloat16 *Ahi, *Alo, *W1hi, *W1lo, *W2hi, *W2lo, *Thi, *Tlo;
    __nv_bfloat16 *Qh, *Ql, *Kh, *Kl, *Vh, *Vl;
    cudaGetSymbolAddress((void**)&qkv,  g_qkv);
    cudaGetSymbolAddress((void**)&Ahi,  g_A_hi);
    cudaGetSymbolAddress((void**)&Alo,  g_A_lo);
    cudaGetSymbolAddress((void**)&W1hi, g_W1_hi);
    cudaGetSymbolAddress((void**)&W1lo, g_W1_lo);
    cudaGetSymbolAddress((void**)&W2hi, g_W2_hi);
    cudaGetSymbolAddress((void**)&W2lo, g_W2_lo);
    cudaGetSymbolAddress((void**)&Thi,  g_att_hi);
    cudaGetSymbolAddress((void**)&Tlo,  g_att_lo);
    cudaGetSymbolAddress((void**)&Qh,   g_Qh);
    cudaGetSymbolAddress((void**)&Ql,   g_Ql);
    cudaGetSymbolAddress((void**)&Kh,   g_Kh);
    cudaGetSymbolAddress((void**)&Kl,   g_Kl);
    cudaGetSymbolAddress((void**)&Vh,   g_Vh);
    cudaGetSymbolAddress((void**)&Vl,   g_Vl);

    const size_t gemm_smem = 8 * (size_t)STG_H * 2;   // 81920 B
    cudaFuncSetAttribute(gemm_mma,
                         cudaFuncAttributeMaxDynamicSharedMemorySize, (int)gemm_smem);
    cudaFuncSetAttribute(attn_mma,
                         cudaFuncAttributeMaxDynamicSharedMemorySize, ATT_SMEM);

    // 0) split inputs + weights into bf16 (hi, lo)
    split_kernel<<<(MTOT * EMB) / 1024, 256>>>(query, Ahi, Alo, MTOT * EMB);
    split_kernel<<<(3 * EMB * EMB) / 1024, 256>>>(Wqkv, W1hi, W1lo, 3 * EMB * EMB);
    split_kernel<<<(EMB * EMB) / 1024, 256>>>(Wo, W2hi, W2lo, EMB * EMB);

    // 1) QKV projection
    {
        dim3 grid(3 * EMB / 128, MTOT / 128);
        gemm_mma<<<grid, 256, gemm_smem>>>(Ahi, Alo, W1hi, W1lo, bqkv, qkv,
                                           MTOT, 3 * EMB, EMB);
    }

    // 2) re-layout qkv -> head-major bf16 hi/lo (Q pre-scaled)
    {
        dim3 grid((MTOT * EMB) / 1024, 3);
        qkv_split<<<grid, 256>>>(qkv, Qh, Ql, Kh, Kl, Vh, Vl);
    }

    // 3) flash attention, writes bf16 hi/lo attention output
    {
        dim3 grid(SEQ / 128, NH, BATCH);
        attn_mma<<<grid, 256, ATT_SMEM>>>(attn_bias, maskp, Thi, Tlo,
                                          Qh, Ql, Kh, Kl, Vh, Vl);
    }

    // 4) output projection
    {
        dim3 grid(EMB / 128, MTOT / 128);
        gemm_mma<<<grid, 256, gemm_smem>>>(Thi, Tlo, W2hi, W2lo, bo, out,
                                           MTOT, EMB, EMB);
    }
}

// round 6
// speedup vs baseline: 1.1539x; 1.1539x over previous
#include <cuda_runtime.h>
#include <cuda_bf16.h>
#include <cstdint>

// Problem constants
#define EMB   1024
#define NH    16
#define HD    64
#define BATCH 4
#define SEQ   1024
#define MTOT  (BATCH*SEQ)
#define SCALING 0.3952847075210474f   // (64*0.1)^-0.5
#define NEG   (-1e30f)

// Scratch (device globals)
__device__ float g_qkv[MTOT * 3 * EMB];
__device__ __nv_bfloat16 g_A_hi[MTOT * EMB];
__device__ __nv_bfloat16 g_A_lo[MTOT * EMB];
__device__ __nv_bfloat16 g_W1_hi[3 * EMB * EMB];
__device__ __nv_bfloat16 g_W1_lo[3 * EMB * EMB];
__device__ __nv_bfloat16 g_W2_hi[EMB * EMB];
__device__ __nv_bfloat16 g_W2_lo[EMB * EMB];
__device__ __nv_bfloat16 g_att_hi[MTOT * EMB];
__device__ __nv_bfloat16 g_att_lo[MTOT * EMB];
__device__ __nv_bfloat16 g_Qh[MTOT * EMB];
__device__ __nv_bfloat16 g_Ql[MTOT * EMB];
__device__ __nv_bfloat16 g_Kh[MTOT * EMB];
__device__ __nv_bfloat16 g_Kl[MTOT * EMB];
__device__ __nv_bfloat16 g_Vh[MTOT * EMB];
__device__ __nv_bfloat16 g_Vl[MTOT * EMB];

// ---------------------------------------------------------------------------
// PTX helpers
// ---------------------------------------------------------------------------
#define LDSM4(r, addr) \
    asm volatile("ldmatrix.sync.aligned.m8n8.x4.shared.b16 {%0,%1,%2,%3}, [%4];" \
                 : "=r"((r)[0]), "=r"((r)[1]), "=r"((r)[2]), "=r"((r)[3]) : "r"(addr))

#define LDSM4T(r, addr) \
    asm volatile("ldmatrix.sync.aligned.m8n8.x4.trans.shared.b16 {%0,%1,%2,%3}, [%4];" \
                 : "=r"((r)[0]), "=r"((r)[1]), "=r"((r)[2]), "=r"((r)[3]) : "r"(addr))

#define MMA_BF16(d, a, b) \
    asm volatile("mma.sync.aligned.m16n8k16.row.col.f32.bf16.bf16.f32 " \
                 "{%0,%1,%2,%3},{%4,%5,%6,%7},{%8,%9},{%0,%1,%2,%3};" \
                 : "+f"((d)[0]), "+f"((d)[1]), "+f"((d)[2]), "+f"((d)[3]) \
                 : "r"((a)[0]), "r"((a)[1]), "r"((a)[2]), "r"((a)[3]), \
                   "r"((b)[0]), "r"((b)[1]))

__device__ __forceinline__ void cp16(uint32_t s, const void* g) {
    asm volatile("cp.async.cg.shared.global [%0], [%1], 16;" :: "r"(s), "l"(g));
}

__device__ __forceinline__ uint32_t packbf(float lo, float hi) {
    uint32_t r;
    asm("cvt.rn.bf16x2.f32 %0, %1, %2;" : "=r"(r) : "f"(hi), "f"(lo));
    return r;
}
__device__ __forceinline__ uint32_t residpack(uint32_t ph, float lo, float hi) {
    float h_lo = __uint_as_float(ph << 16);
    float h_hi = __uint_as_float(ph & 0xffff0000u);
    return packbf(lo - h_lo, hi - h_hi);
}

// ---------------------------------------------------------------------------
// f32 -> bf16 (hi, lo) split
// ---------------------------------------------------------------------------
__global__ __launch_bounds__(256)
void split_kernel(const float* __restrict__ in,
                  __nv_bfloat16* __restrict__ hi,
                  __nv_bfloat16* __restrict__ lo, int n)
{
    int i = (blockIdx.x * blockDim.x + threadIdx.x) * 4;
    if (i >= n) return;
    float4 v = *(const float4*)(in + i);
    float f[4] = {v.x, v.y, v.z, v.w};
    __nv_bfloat16 h[4], l[4];
#pragma unroll
    for (int j = 0; j < 4; j++) {
        h[j] = __float2bfloat16(f[j]);
        l[j] = __float2bfloat16(f[j] - __bfloat162float(h[j]));
    }
    *(uint2*)(hi + i) = *(const uint2*)h;
    *(uint2*)(lo + i) = *(const uint2*)l;
}

// ---------------------------------------------------------------------------
// qkv f32 -> head-major bf16 hi/lo [b,h,s,64]; Q pre-scaled
// ---------------------------------------------------------------------------
__global__ __launch_bounds__(256)
void qkv_split(const float* __restrict__ qkv,
               __nv_bfloat16* __restrict__ Qh, __nv_bfloat16* __restrict__ Ql,
               __nv_bfloat16* __restrict__ Kh, __nv_bfloat16* __restrict__ Kl,
               __nv_bfloat16* __restrict__ Vh, __nv_bfloat16* __restrict__ Vl)
{
    int m = blockIdx.y;
    int i = (blockIdx.x * 256 + threadIdx.x) * 4;
    int row = i >> 10, col = i & 1023;
    float4 v = *(const float4*)(qkv + (size_t)row * 3072 + m * 1024 + col);
    if (m == 0) { v.x *= SCALING; v.y *= SCALING; v.z *= SCALING; v.w *= SCALING; }
    int bb = row >> 10, s = row & 1023, hh = col >> 6, d = col & 63;
    size_t o = (((size_t)(bb * NH + hh)) * SEQ + s) * HD + d;
    __nv_bfloat16* hi = (m == 0) ? Qh : (m == 1) ? Kh : Vh;
    __nv_bfloat16* lo = (m == 0) ? Ql : (m == 1) ? Kl : Vl;
    float f[4] = {v.x, v.y, v.z, v.w};
    __nv_bfloat16 hb4[4], lb4[4];
#pragma unroll
    for (int j = 0; j < 4; j++) {
        hb4[j] = __float2bfloat16(f[j]);
        lb4[j] = __float2bfloat16(f[j] - __bfloat162float(hb4[j]));
    }
    *(uint2*)(hi + o) = *(const uint2*)hb4;
    *(uint2*)(lo + o) = *(const uint2*)lb4;
}

// ---------------------------------------------------------------------------
// Tensor-core GEMM: C[M,N] = A[M,K]*B[N,K]^T + bias[N], 3-term bf16 split.
// CTA 128x128, 128 threads (4 warps, 2m x 2n), warp tile 64x64, BK=32.
// 64x64 warp tile: 16 LDSM4 per 96 MMAs (85 B/MMA vs 128 in the 32x64 tile).
// ---------------------------------------------------------------------------
#define AST   40            // smem row stride in halves
#define MAT_H (128 * AST)   // halves per matrix per stage

__global__ __launch_bounds__(128, 2)
void gemm_mma(const __nv_bfloat16* __restrict__ Ah,
              const __nv_bfloat16* __restrict__ Al,
              const __nv_bfloat16* __restrict__ Bh,
              const __nv_bfloat16* __restrict__ Bl,
              const float* __restrict__ bias,
              float* __restrict__ C, int M, int N, int K)
{
    extern __shared__ __align__(16) __nv_bfloat16 smem_b[];
    const uint32_t sm_base = (uint32_t)__cvta_generic_to_shared(smem_b);

    const int t    = threadIdx.x;
    const int lane = t & 31;
    const int w    = t >> 5;
    const int wm   = w & 1;     // m-warp (2)
    const int wn   = w >> 1;    // n-warp (2)
    const int bm   = blockIdx.y * 128;
    const int bn   = blockIdx.x * 128;
    const int nk   = K >> 5;

    float acc[4][8][4];
#pragma unroll
    for (int mi = 0; mi < 4; mi++)
#pragma unroll
        for (int ni = 0; ni < 8; ni++)
#pragma unroll
            for (int q = 0; q < 4; q++) acc[mi][ni][q] = 0.f;

    const __nv_bfloat16* gp[4] = {Ah, Al, Bh, Bl};

    // 16 cp.async chunks per thread per stage (4 matrices x 512 chunks)
    auto issue = [&](int stage, int k0) {
#pragma unroll
        for (int i = 0; i < 16; i++) {
            int c = t + i * 128;
            int mat = c >> 9;
            int idx = c & 511;
            int row = idx >> 2, ck = (idx & 3) * 8;
            int base = (mat < 2) ? bm : bn;
            uint32_t so = sm_base + (uint32_t)(stage * 4 + mat) * MAT_H * 2;
            cp16(so + (uint32_t)(row * AST + ck) * 2,
                 gp[mat] + (size_t)(base + row) * K + k0 + ck);
        }
        asm volatile("cp.async.commit_group;");
    };

    issue(0, 0);
    issue(1, 32);

    for (int kt = 0; kt < nk; kt++) {
        if (kt + 1 < nk) asm volatile("cp.async.wait_group 1;");
        else             asm volatile("cp.async.wait_group 0;");
        __syncthreads();

        const int stage = kt & 1;
        const uint32_t bAh = sm_base + (uint32_t)(stage * 4 + 0) * MAT_H * 2;
        const uint32_t bAl = sm_base + (uint32_t)(stage * 4 + 1) * MAT_H * 2;
        const uint32_t bBh = sm_base + (uint32_t)(stage * 4 + 2) * MAT_H * 2;
        const uint32_t bBl = sm_base + (uint32_t)(stage * 4 + 3) * MAT_H * 2;

#pragma unroll
        for (int ks = 0; ks < 2; ks++) {
            uint32_t ah[4][4], al[4][4], bh[8][2], bl[8][2];

            const int arow = wm * 64 + (lane & 15);
            const int acol = ks * 16 + (lane >> 4) * 8;
#pragma unroll
            for (int mi = 0; mi < 4; mi++) {
                uint32_t off = (uint32_t)((arow + mi * 16) * AST + acol) * 2;
                LDSM4(ah[mi], bAh + off);
                LDSM4(al[mi], bAl + off);
            }

            const int brow = wn * 64 + (lane >> 4) * 8 + (lane & 7);
            const int bcol = ks * 16 + ((lane >> 3) & 1) * 8;
#pragma unroll
            for (int ni2 = 0; ni2 < 4; ni2++) {
                uint32_t off = (uint32_t)((brow + ni2 * 16) * AST + bcol) * 2;
                uint32_t r[4];
                LDSM4(r, bBh + off);
                bh[ni2 * 2][0] = r[0]; bh[ni2 * 2][1] = r[1];
                bh[ni2 * 2 + 1][0] = r[2]; bh[ni2 * 2 + 1][1] = r[3];
                LDSM4(r, bBl + off);
                bl[ni2 * 2][0] = r[0]; bl[ni2 * 2][1] = r[1];
                bl[ni2 * 2 + 1][0] = r[2]; bl[ni2 * 2 + 1][1] = r[3];
            }

#pragma unroll
            for (int mi = 0; mi < 4; mi++)
#pragma unroll
                for (int ni = 0; ni < 8; ni++) {
                    MMA_BF16(acc[mi][ni], ah[mi], bh[ni]);   // hi*hi
                    MMA_BF16(acc[mi][ni], al[mi], bh[ni]);   // lo*hi
                    MMA_BF16(acc[mi][ni], ah[mi], bl[ni]);   // hi*lo
                }
        }
        __syncthreads();

        if (kt + 2 < nk) issue(kt & 1, (kt + 2) << 5);
    }

    // epilogue
#pragma unroll
    for (int mi = 0; mi < 4; mi++) {
        const int r0 = bm + wm * 64 + mi * 16 + (lane >> 2);
#pragma unroll
        for (int ni = 0; ni < 8; ni++) {
            const int col = bn + wn * 64 + ni * 8 + (lane & 3) * 2;
            float bx = bias[col], by = bias[col + 1];
            float2 v0 = make_float2(acc[mi][ni][0] + bx, acc[mi][ni][1] + by);
            float2 v1 = make_float2(acc[mi][ni][2] + bx, acc[mi][ni][3] + by);
            *(float2*)&C[(size_t)r0 * N + col] = v0;
            *(float2*)&C[(size_t)(r0 + 8) * N + col] = v1;
        }
    }
}
#define GEMM_SMEM (8 * MAT_H * 2)   // 81920 B (2 stages x 4 matrices)

// ---------------------------------------------------------------------------
// Tensor-core flash attention (R3 interleaved order) + bf16 hi/lo epilogue.
// ---------------------------------------------------------------------------
#define AT_ST 72
#define Q_HI_B 0
#define Q_LO_B 18432
#define TILE_B 36864
#define ATT_MAT_B  9216
#define BUF_B  36864
#define ATT_SMEM 110592

__global__ __launch_bounds__(256)
void attn_mma(const float* __restrict__ bias, const unsigned char* __restrict__ mask,
              __nv_bfloat16* __restrict__ outh, __nv_bfloat16* __restrict__ outl,
              const __nv_bfloat16* __restrict__ Qh, const __nv_bfloat16* __restrict__ Ql,
              const __nv_bfloat16* __restrict__ Kh, const __nv_bfloat16* __restrict__ Kl,
              const __nv_bfloat16* __restrict__ Vh, const __nv_bfloat16* __restrict__ Vl)
{
    extern __shared__ __align__(16) __nv_bfloat16 smA[];
    const uint32_t s_base = (uint32_t)__cvta_generic_to_shared(smA);

    const int t = threadIdx.x, lane = t & 31, wid = t >> 5;
    const int qt = blockIdx.x, h = blockIdx.y, b = blockIdx.z;
    const int qbase = qt * 128;
    const size_t hb = (size_t)(b * NH + h) * SEQ * HD;

    const int lr7 = lane & 7, l8 = (lane >> 3) & 1, l16 = lane >> 4;

    const __nv_bfloat16* qsrc[2] = {Qh, Ql};
    const __nv_bfloat16* ksrc[4] = {Kh, Kl, Vh, Vl};

#pragma unroll
    for (int it = 0; it < 8; it++) {
        int c = t + it * 256;
        int mat = c >> 10, r = (c >> 3) & 127, ck = c & 7;
        cp16(s_base + mat * Q_LO_B + (uint32_t)(r * AT_ST + ck * 8) * 2,
             qsrc[mat] + hb + (size_t)(qbase + r) * HD + ck * 8);
    }
#pragma unroll
    for (int it = 0; it < 8; it++) {
        int c = t + it * 256;
        int mat = c >> 9, r = (c >> 3) & 63, ck = c & 7;
        cp16(s_base + TILE_B + mat * ATT_MAT_B + (uint32_t)(r * AT_ST + ck * 8) * 2,
             ksrc[mat] + hb + (size_t)r * HD + ck * 8);
    }
    asm volatile("cp.async.commit_group;");
#pragma unroll
    for (int it = 0; it < 8; it++) {
        int c = t + it * 256;
        int mat = c >> 9, r = (c >> 3) & 63, ck = c & 7;
        cp16(s_base + TILE_B + BUF_B + mat * ATT_MAT_B + (uint32_t)(r * AT_ST + ck * 8) * 2,
             ksrc[mat] + hb + (size_t)(64 + r) * HD + ck * 8);
    }
    asm volatile("cp.async.commit_group;");
    asm volatile("cp.async.wait_group 1;");
    __syncthreads();

    uint32_t aqh[4][4], aql[4][4];
    {
        const int arow = wid * 16 + (lane & 15);
        const int acol = 8 * l16;
#pragma unroll
        for (int ks = 0; ks < 4; ks++) {
            uint32_t off = (uint32_t)(arow * AT_ST + ks * 16 + acol) * 2;
            LDSM4(aqh[ks], s_base + Q_HI_B + off);
            LDSM4(aql[ks], s_base + Q_LO_B + off);
        }
    }

    float O[8][4];
#pragma unroll
    for (int nf = 0; nf < 8; nf++)
#pragma unroll
        for (int q = 0; q < 4; q++) O[nf][q] = 0.f;
    float m0 = NEG, m1 = NEG, l0 = 0.f, l1 = 0.f;

    const float* bp = bias + (size_t)(b * NH + h) * SEQ * SEQ;
    const unsigned char* mrow = mask + (size_t)b * SEQ;
    const int qr = qbase + wid * 16 + (lane >> 2);
    const int colb = 2 * (lane & 3);

    const int krow = lr7 + 8 * l16;
    const int kcol = 8 * l8;
    const int vrow = lr7 + 8 * l8;
    const int vcol = 8 * l16;

    for (int kt = 0; kt < 16; kt++) {
        const uint32_t tb = s_base + TILE_B + (uint32_t)(kt & 1) * BUF_B;

        float2 bv0[8], bv1[8];
        uchar2 mk[8];
#pragma unroll
        for (int nf = 0; nf < 8; nf++) {
            int col = kt * 64 + nf * 8 + colb;
            bv0[nf] = *(const float2*)&bp[(size_t)qr * SEQ + col];
            bv1[nf] = *(const float2*)&bp[(size_t)(qr + 8) * SEQ + col];
            mk[nf]  = *(const uchar2*)&mrow[col];
        }

        float s[8][4];
#pragma unroll
        for (int nf = 0; nf < 8; nf++)
#pragma unroll
            for (int q = 0; q < 4; q++) s[nf][q] = 0.f;

#pragma unroll
        for (int ks = 0; ks < 4; ks++) {
            uint32_t bh[8][2], bl[8][2];
#pragma unroll
            for (int nf2 = 0; nf2 < 4; nf2++) {
                uint32_t off = (uint32_t)((nf2 * 16 + krow) * AT_ST + ks * 16 + kcol) * 2;
                uint32_t r4[4];
                LDSM4(r4, tb + 0 * ATT_MAT_B + off);
                bh[2*nf2][0] = r4[0]; bh[2*nf2][1] = r4[1];
                bh[2*nf2+1][0] = r4[2]; bh[2*nf2+1][1] = r4[3];
                LDSM4(r4, tb + 1 * ATT_MAT_B + off);
                bl[2*nf2][0] = r4[0]; bl[2*nf2][1] = r4[1];
                bl[2*nf2+1][0] = r4[2]; bl[2*nf2+1][1] = r4[3];
            }
#pragma unroll
            for (int nf = 0; nf < 8; nf++) {
                MMA_BF16(s[nf], aqh[ks], bh[nf]);
                MMA_BF16(s[nf], aql[ks], bh[nf]);
                MMA_BF16(s[nf], aqh[ks], bl[nf]);
            }
        }

#pragma unroll
        for (int nf = 0; nf < 8; nf++) {
            s[nf][0] = mk[nf].x ? NEG : s[nf][0] + bv0[nf].x;
            s[nf][1] = mk[nf].y ? NEG : s[nf][1] + bv0[nf].y;
            s[nf][2] = mk[nf].x ? NEG : s[nf][2] + bv1[nf].x;
            s[nf][3] = mk[nf].y ? NEG : s[nf][3] + bv1[nf].y;
        }

        float mx0 = NEG, mx1 = NEG;
#pragma unroll
        for (int nf = 0; nf < 8; nf++) {
            mx0 = fmaxf(mx0, fmaxf(s[nf][0], s[nf][1]));
            mx1 = fmaxf(mx1, fmaxf(s[nf][2], s[nf][3]));
        }
        mx0 = fmaxf(mx0, __shfl_xor_sync(0xffffffffu, mx0, 1));
        mx0 = fmaxf(mx0, __shfl_xor_sync(0xffffffffu, mx0, 2));
        mx1 = fmaxf(mx1, __shfl_xor_sync(0xffffffffu, mx1, 1));
        mx1 = fmaxf(mx1, __shfl_xor_sync(0xffffffffu, mx1, 2));
        float mn0 = fmaxf(m0, mx0), mn1 = fmaxf(m1, mx1);
        float sc0 = __expf(m0 - mn0), sc1 = __expf(m1 - mn1);
        m0 = mn0; m1 = mn1;
        float su0 = 0.f, su1 = 0.f;
#pragma unroll
        for (int nf = 0; nf < 8; nf++) {
            s[nf][0] = __expf(s[nf][0] - mn0);
            s[nf][1] = __expf(s[nf][1] - mn0);
            s[nf][2] = __expf(s[nf][2] - mn1);
            s[nf][3] = __expf(s[nf][3] - mn1);
            su0 += s[nf][0] + s[nf][1];
            su1 += s[nf][2] + s[nf][3];
        }
        su0 += __shfl_xor_sync(0xffffffffu, su0, 1);
        su0 += __shfl_xor_sync(0xffffffffu, su0, 2);
        su1 += __shfl_xor_sync(0xffffffffu, su1, 1);
        su1 += __shfl_xor_sync(0xffffffffu, su1, 2);
        l0 = l0 * sc0 + su0;
        l1 = l1 * sc1 + su1;
#pragma unroll
        for (int nf = 0; nf < 8; nf++) {
            O[nf][0] *= sc0; O[nf][1] *= sc0;
            O[nf][2] *= sc1; O[nf][3] *= sc1;
        }

#pragma unroll
        for (int ks = 0; ks < 4; ks++) {
            uint32_t aph[4], apl[4];
            {
                const float* p0 = s[2 * ks];
                const float* p1 = s[2 * ks + 1];
                aph[0] = packbf(p0[0], p0[1]);
                aph[1] = packbf(p0[2], p0[3]);
                aph[2] = packbf(p1[0], p1[1]);
                aph[3] = packbf(p1[2], p1[3]);
                apl[0] = residpack(aph[0], p0[0], p0[1]);
                apl[1] = residpack(aph[1], p0[2], p0[3]);
                apl[2] = residpack(aph[2], p1[0], p1[1]);
                apl[3] = residpack(aph[3], p1[2], p1[3]);
            }
            uint32_t vh[8][2], vl[8][2];
#pragma unroll
            for (int nf2 = 0; nf2 < 4; nf2++) {
                uint32_t off = (uint32_t)((ks * 16 + vrow) * AT_ST + nf2 * 16 + vcol) * 2;
                uint32_t r4[4];
                LDSM4T(r4, tb + 2 * ATT_MAT_B + off);
                vh[2*nf2][0] = r4[0]; vh[2*nf2][1] = r4[1];
                vh[2*nf2+1][0] = r4[2]; vh[2*nf2+1][1] = r4[3];
                LDSM4T(r4, tb + 3 * ATT_MAT_B + off);
                vl[2*nf2][0] = r4[0]; vl[2*nf2][1] = r4[1];
                vl[2*nf2+1][0] = r4[2]; vl[2*nf2+1][1] = r4[3];
            }
#pragma unroll
            for (int nf = 0; nf < 8; nf++) {
                MMA_BF16(O[nf], aph, vh[nf]);
                MMA_BF16(O[nf], apl, vh[nf]);
                MMA_BF16(O[nf], aph, vl[nf]);
            }
        }

        __syncthreads();
        if (kt + 2 < 16) {
#pragma unroll
            for (int it = 0; it < 8; it++) {
                int c = t + it * 256;
                int mat = c >> 9, r = (c >> 3) & 63, ck = c & 7;
                cp16(s_base + TILE_B + (uint32_t)(kt & 1) * BUF_B + mat * ATT_MAT_B +
                         (uint32_t)(r * AT_ST + ck * 8) * 2,
                     ksrc[mat] + hb + (size_t)((kt + 2) * 64 + r) * HD + ck * 8);
            }
            asm volatile("cp.async.commit_group;");
        }
        if (kt + 1 < 16) {
            if (kt + 2 < 16) asm volatile("cp.async.wait_group 1;");
            else             asm volatile("cp.async.wait_group 0;");
            __syncthreads();
        }
    }

    // epilogue: write bf16 hi/lo directly (feeds out-proj GEMM, no split pass)
    float i0 = 1.f / l0, i1 = 1.f / l1;
    int orow = b * SEQ + qbase + wid * 16 + (lane >> 2);
    uint32_t* oh = (uint32_t*)outh;
    uint32_t* ol = (uint32_t*)outl;
#pragma unroll
    for (int nf = 0; nf < 8; nf++) {
        int col = h * HD + nf * 8 + colb;
        float a0 = O[nf][0] * i0, a1 = O[nf][1] * i0;
        float b0 = O[nf][2] * i1, b1 = O[nf][3] * i1;
        uint32_t h0 = packbf(a0, a1);
        uint32_t l0r = residpack(h0, a0, a1);
        uint32_t h1 = packbf(b0, b1);
        uint32_t l1r = residpack(h1, b0, b1);
        size_t idx0 = ((size_t)orow * EMB + col) >> 1;
        size_t idx1 = ((size_t)(orow + 8) * EMB + col) >> 1;
        oh[idx0] = h0; ol[idx0] = l0r;
        oh[idx1] = h1; ol[idx1] = l1r;
    }
}

// ---------------------------------------------------------------------------
extern "C" void kernel_launch(void* const* d_in, const int* in_sizes, int n_in,
                              void* d_out, int out_size)
{
    const float* query         = (const float*)d_in[0];
    const unsigned char* maskp = (const unsigned char*)d_in[1];
    const float* attn_bias     = (const float*)d_in[2];
    const float* Wqkv          = (const float*)d_in[3];
    const float* bqkv          = (const float*)d_in[4];
    const float* Wo            = (const float*)d_in[5];
    const float* bo            = (const float*)d_in[6];
    float* out                 = (float*)d_out;

    float* qkv;
    __nv_bfloat16 *Ahi, *Alo, *W1hi, *W1lo, *W2hi, *W2lo, *Thi, *Tlo;
    __nv_bfloat16 *Qh, *Ql, *Kh, *Kl, *Vh, *Vl;
    cudaGetSymbolAddress((void**)&qkv,  g_qkv);
    cudaGetSymbolAddress((void**)&Ahi,  g_A_hi);
    cudaGetSymbolAddress((void**)&Alo,  g_A_lo);
    cudaGetSymbolAddress((void**)&W1hi, g_W1_hi);
    cudaGetSymbolAddress((void**)&W1lo, g_W1_lo);
    cudaGetSymbolAddress((void**)&W2hi, g_W2_hi);
    cudaGetSymbolAddress((void**)&W2lo, g_W2_lo);
    cudaGetSymbolAddress((void**)&Thi,  g_att_hi);
    cudaGetSymbolAddress((void**)&Tlo,  g_att_lo);
    cudaGetSymbolAddress((void**)&Qh,   g_Qh);
    cudaGetSymbolAddress((void**)&Ql,   g_Ql);
    cudaGetSymbolAddress((void**)&Kh,   g_Kh);
    cudaGetSymbolAddress((void**)&Kl,   g_Kl);
    cudaGetSymbolAddress((void**)&Vh,   g_Vh);
    cudaGetSymbolAddress((void**)&Vl,   g_Vl);

    cudaFuncSetAttribute(gemm_mma,
                         cudaFuncAttributeMaxDynamicSharedMemorySize, GEMM_SMEM);
    cudaFuncSetAttribute(attn_mma,
                         cudaFuncAttributeMaxDynamicSharedMemorySize, ATT_SMEM);

    // 0) split inputs + weights into bf16 (hi, lo)
    split_kernel<<<(MTOT * EMB) / 1024, 256>>>(query, Ahi, Alo, MTOT * EMB);
    split_kernel<<<(3 * EMB * EMB) / 1024, 256>>>(Wqkv, W1hi, W1lo, 3 * EMB * EMB);
    split_kernel<<<(EMB * EMB) / 1024, 256>>>(Wo, W2hi, W2lo, EMB * EMB);

    // 1) QKV projection
    {
        dim3 grid(3 * EMB / 128, MTOT / 128);
        gemm_mma<<<grid, 128, GEMM_SMEM>>>(Ahi, Alo, W1hi, W1lo, bqkv, qkv,
                                           MTOT, 3 * EMB, EMB);
    }

    // 2) re-layout qkv -> head-major bf16 hi/lo (Q pre-scaled)
    {
        dim3 grid((MTOT * EMB) / 1024, 3);
        qkv_split<<<grid, 256>>>(qkv, Qh, Ql, Kh, Kl, Vh, Vl);
    }

    // 3) flash attention, writes bf16 hi/lo attention output
    {
        dim3 grid(SEQ / 128, NH, BATCH);
        attn_mma<<<grid, 256, ATT_SMEM>>>(attn_bias, maskp, Thi, Tlo,
                                          Qh, Ql, Kh, Kl, Vh, Vl);
    }

    // 4) output projection
    {
        dim3 grid(EMB / 128, MTOT / 128);
        gemm_mma<<<grid, 128, GEMM_SMEM>>>(Thi, Tlo, W2hi, W2lo, bo, out,
                                           MTOT, EMB, EMB);
    }
}